// round 15
// baseline (speedup 1.0000x reference)
#include <cuda_runtime.h>
#include <cuda_fp16.h>
#include <cstdint>

#define DHW 256

// Every-z 8-corner table over the contracted window (R14 design; sample hot
// path measured at 63.4us — body kept verbatim, now inside a persistent
// grid-stride loop to eliminate wave-transition overhead and tail spread).
// Exact bound: |coord| <= 0.625 -> ix in [47.8, 207.2] -> x0 in [47, 207].
// WLO=44 (multiple of 4 for aligned convert reads), WS=164 covers [44, 207].
// Entry (zi, yi, xi), fp16 pairs:
//  .x=(v[z][y][x],   v[z][y][x+1])    .y=(v[z][y+1][x],   v[z][y+1][x+1])
//  .z=(v[z+1][y][x], v[z+1][y][x+1])  .w=(v[z+1][y+1][x], v[z+1][y+1][x+1])
// One aligned 16B load = all 8 corners. 164^3*16B = 70.6 MB.
#define WLO 44
#define WS  164
__device__ __align__(32) uint4 g_quad[WS * WS * WS];

__device__ __forceinline__ uint64_t make_policy_evict_last() {
    uint64_t pol;
    asm("createpolicy.fractional.L2::evict_last.b64 %0, 1.0;" : "=l"(pol));
    return pol;
}

__device__ __forceinline__ uint4 ldg_evict_last(const uint4* p, uint64_t pol) {
    uint4 v;
    asm volatile("ld.global.nc.L2::cache_hint.v4.u32 {%0,%1,%2,%3}, [%4], %5;"
                 : "=r"(v.x), "=r"(v.y), "=r"(v.z), "=r"(v.w)
                 : "l"(p), "l"(pol));
    return v;
}

// 256-bit evict_last store (sm_103a .v8.b32): 32B per instruction.
__device__ __forceinline__ void stg256_evict_last(uint4* p, uint4 a, uint4 b) {
    asm volatile("st.global.L2::evict_last.v8.b32 [%0], {%1,%2,%3,%4,%5,%6,%7,%8};"
                 :: "l"(p),
                    "r"(a.x), "r"(a.y), "r"(a.z), "r"(a.w),
                    "r"(b.x), "r"(b.y), "r"(b.z), "r"(b.w)
                 : "memory");
}

// Convert: thread = (x-group of 4, y, z-block of 4) with rolling z rows.
#define ZCH 4
#define CONV_XG (WS / 4)                        // 41
#define CONV_ZB (WS / ZCH)                      // 41
#define CONV_TOTAL (CONV_XG * WS * CONV_ZB)

__global__ void __launch_bounds__(256)
convert_kernel(const float* __restrict__ vol) {
    int t = blockIdx.x * blockDim.x + threadIdx.x;
    if (t >= CONV_TOTAL) return;
    int xg = t % CONV_XG;
    int yi = (t / CONV_XG) % WS;
    int zb = t / (CONV_XG * WS);

    int x  = WLO + (xg << 2);    // 16B-aligned
    int y  = WLO + yi;
    int z0 = WLO + zb * ZCH;

    const float* base0 = vol + ((z0 << 16) | (y << 8) | x);

    float4 a0 = __ldg((const float4*)base0);          float a0e = __ldg(base0 + 4);
    float4 a1 = __ldg((const float4*)(base0 + 256));  float a1e = __ldg(base0 + 256 + 4);
    float A0[5] = {a0.x, a0.y, a0.z, a0.w, a0e};
    float A1[5] = {a1.x, a1.y, a1.z, a1.w, a1e};

    uint4* dst = g_quad + (((zb * ZCH) * WS + yi) * WS + (xg << 2));

    #pragma unroll
    for (int dz = 0; dz < ZCH; dz++) {
        const float* basen = base0 + ((dz + 1) << 16);
        float4 b0 = __ldg((const float4*)basen);          float b0e = __ldg(basen + 4);
        float4 b1 = __ldg((const float4*)(basen + 256));  float b1e = __ldg(basen + 256 + 4);
        float B0[5] = {b0.x, b0.y, b0.z, b0.w, b0e};
        float B1[5] = {b1.x, b1.y, b1.z, b1.w, b1e};

        uint4 w[4];
        #pragma unroll
        for (int j = 0; j < 4; j++) {
            __half2 e0 = __floats2half2_rn(A0[j], A0[j + 1]);   // z,   y
            __half2 e1 = __floats2half2_rn(A1[j], A1[j + 1]);   // z,   y+1
            __half2 f0 = __floats2half2_rn(B0[j], B0[j + 1]);   // z+1, y
            __half2 f1 = __floats2half2_rn(B1[j], B1[j + 1]);   // z+1, y+1
            w[j].x = *(unsigned*)&e0; w[j].y = *(unsigned*)&e1;
            w[j].z = *(unsigned*)&f0; w[j].w = *(unsigned*)&f1;
        }
        stg256_evict_last(dst,     w[0], w[1]);
        stg256_evict_last(dst + 2, w[2], w[3]);

        dst += WS * WS;
        #pragma unroll
        for (int j = 0; j < 5; j++) { A0[j] = B0[j]; A1[j] = B1[j]; }
    }
}

// Exact fp32 path (out-of-window fallback and cs == 0).
__device__ __forceinline__ float gather(const float* __restrict__ vol,
                                        int z, int y, int x) {
    if ((unsigned)z < (unsigned)DHW &&
        (unsigned)y < (unsigned)DHW &&
        (unsigned)x < (unsigned)DHW) {
        return __ldg(vol + ((z << 16) | (y << 8) | x));
    }
    return 0.0f;
}

__device__ __noinline__ float sample_fp32(const float* __restrict__ vol,
                                          float ix, float iy, float iz) {
    float x0f = floorf(ix), y0f = floorf(iy), z0f = floorf(iz);
    float tx = ix - x0f, ty = iy - y0f, tz = iz - z0f;
    int x0 = (int)x0f, y0 = (int)y0f, z0 = (int)z0f;
    float v000 = gather(vol, z0, y0, x0);
    float v001 = gather(vol, z0, y0, x0 + 1);
    float v010 = gather(vol, z0, y0 + 1, x0);
    float v011 = gather(vol, z0, y0 + 1, x0 + 1);
    float v100 = gather(vol, z0 + 1, y0, x0);
    float v101 = gather(vol, z0 + 1, y0, x0 + 1);
    float v110 = gather(vol, z0 + 1, y0 + 1, x0);
    float v111 = gather(vol, z0 + 1, y0 + 1, x0 + 1);
    float c00 = v000 + tx * (v001 - v000);
    float c01 = v010 + tx * (v011 - v010);
    float c10 = v100 + tx * (v101 - v100);
    float c11 = v110 + tx * (v111 - v110);
    float c0  = c00 + ty * (c01 - c00);
    float c1  = c10 + ty * (c11 - c10);
    return c0 + tz * (c1 - c0);
}

// Persistent grid-stride sample: one wave, no wave-transition overhead.
// Body identical to the measured-63.4us R14 hot path.
__global__ void __launch_bounds__(256)
sample_kernel(const float4* __restrict__ xyz,
              const float* __restrict__ vol,
              const float* __restrict__ aabb,
              const int*   __restrict__ cspace,
              float* __restrict__ out,
              int n) {
    float a0x = __ldg(aabb + 0), a0y = __ldg(aabb + 1), a0z = __ldg(aabb + 2);
    float a1x = __ldg(aabb + 3), a1y = __ldg(aabb + 4), a1z = __ldg(aabb + 5);
    float igx = 2.0f / (a1x - a0x);
    float igy = 2.0f / (a1y - a0y);
    float igz = 2.0f / (a1z - a0z);
    int cs = __ldg(cspace);
    const float half_span = 0.5f * (DHW - 1);
    uint64_t pol = make_policy_evict_last();

    int stride2 = gridDim.x * blockDim.x * 2;

    for (int base = (blockIdx.x * blockDim.x + threadIdx.x) * 2;
         base < n; base += stride2) {
        bool has1 = (base + 1) < n;

        float4 p[2];
        p[0] = __ldcs(xyz + base);
        p[1] = has1 ? __ldcs(xyz + base + 1) : p[0];

        float tx[2], ty[2], tz[2];
        float fix[2], fiy[2], fiz[2];
        int   idx[2];

        #pragma unroll
        for (int j = 0; j < 2; j++) {
            float cx = (p[j].x - a0x) * igx - 1.0f;
            float cy = (p[j].y - a0y) * igy - 1.0f;
            float cz = (p[j].z - a0z) * igz - 1.0f;
            if (cs != 0) {
                float dist = fmaxf(fabsf(cx), fmaxf(fabsf(cy), fabsf(cz))) + 1e-8f;
                float scale = (dist > 1.0f) ? (2.0f - 1.0f / dist) : dist;
                float m = scale * 0.5f / dist;
                cx *= m; cy *= m; cz *= m;
            }
            float ix = (cx + 1.0f) * half_span;
            float iy = (cy + 1.0f) * half_span;
            float iz = (cz + 1.0f) * half_span;
            float x0f = floorf(ix), y0f = floorf(iy), z0f = floorf(iz);
            tx[j] = ix - x0f; ty[j] = iy - y0f; tz[j] = iz - z0f;
            fix[j] = ix; fiy[j] = iy; fiz[j] = iz;
            int xi = (int)x0f - WLO;
            int yi = (int)y0f - WLO;
            int zi = (int)z0f - WLO;
            idx[j] = (cs != 0 &&
                      (unsigned)xi < WS && (unsigned)yi < WS && (unsigned)zi < WS)
                   ? ((zi * WS + yi) * WS + xi) : -1;
        }

        // One 16B evict_last gather per point, issued back-to-back.
        uint4 Q[2];
        Q[0] = (idx[0] >= 0) ? ldg_evict_last(g_quad + idx[0], pol)
                             : make_uint4(0u, 0u, 0u, 0u);
        Q[1] = (idx[1] >= 0) ? ldg_evict_last(g_quad + idx[1], pol)
                             : make_uint4(0u, 0u, 0u, 0u);

        float r[2];
        #pragma unroll
        for (int j = 0; j < 2; j++) {
            if (idx[j] >= 0) {
                float2 l0 = __half22float2(*(__half2*)&Q[j].x);
                float2 l1 = __half22float2(*(__half2*)&Q[j].y);
                float2 h0 = __half22float2(*(__half2*)&Q[j].z);
                float2 h1 = __half22float2(*(__half2*)&Q[j].w);
                float c00 = l0.x + tx[j] * (l0.y - l0.x);
                float c01 = l1.x + tx[j] * (l1.y - l1.x);
                float c10 = h0.x + tx[j] * (h0.y - h0.x);
                float c11 = h1.x + tx[j] * (h1.y - h1.x);
                float c0  = c00 + ty[j] * (c01 - c00);
                float c1  = c10 + ty[j] * (c11 - c10);
                r[j] = c0 + tz[j] * (c1 - c0);
            } else {
                r[j] = sample_fp32(vol, fix[j], fiy[j], fiz[j]);
            }
        }

        if (has1) {
            __stcs((float2*)(out + base), make_float2(r[0], r[1]));
        } else {
            out[base] = r[0];
        }
    }
}

extern "C" void kernel_launch(void* const* d_in, const int* in_sizes, int n_in,
                              void* d_out, int out_size) {
    const float4* xyz  = (const float4*)d_in[0];
    const float*  vol  = (const float*)d_in[1];
    const float*  aabb = (const float*)d_in[2];
    const int*    cs   = (const int*)d_in[3];
    float* out = (float*)d_out;
    int n = out_size;

    convert_kernel<<<(CONV_TOTAL + 255) / 256, 256>>>(vol);

    // Persistent grid: 148 SMs x 6 resident CTAs (40 regs x 256 thr -> 6/SM).
    int threads = 256;
    int blocks = 148 * 6;
    sample_kernel<<<blocks, threads>>>(xyz, vol, aabb, cs, out, n);
}

// round 16
// speedup vs baseline: 1.2228x; 1.2228x over previous
#include <cuda_runtime.h>
#include <cuda_fp16.h>
#include <cstdint>

#define DHW 256

// Every-z 8-corner table over the contracted window (R14 design, measured
// sample 63.4us / convert 14.5us; only change vs R14: xyz pair loaded with a
// single 256-bit load).
// Exact bound: |coord| <= 0.625 -> ix in [47.8, 207.2] -> x0 in [47, 207].
// WLO=44 (multiple of 4 for aligned convert reads), WS=164 covers [44, 207].
// Entry (zi, yi, xi), fp16 pairs:
//  .x=(v[z][y][x],   v[z][y][x+1])    .y=(v[z][y+1][x],   v[z][y+1][x+1])
//  .z=(v[z+1][y][x], v[z+1][y][x+1])  .w=(v[z+1][y+1][x], v[z+1][y+1][x+1])
// One aligned 16B load = all 8 corners. 164^3*16B = 70.6 MB.
#define WLO 44
#define WS  164
__device__ __align__(32) uint4 g_quad[WS * WS * WS];

__device__ __forceinline__ uint64_t make_policy_evict_last() {
    uint64_t pol;
    asm("createpolicy.fractional.L2::evict_last.b64 %0, 1.0;" : "=l"(pol));
    return pol;
}

__device__ __forceinline__ uint4 ldg_evict_last(const uint4* p, uint64_t pol) {
    uint4 v;
    asm volatile("ld.global.nc.L2::cache_hint.v4.u32 {%0,%1,%2,%3}, [%4], %5;"
                 : "=r"(v.x), "=r"(v.y), "=r"(v.z), "=r"(v.w)
                 : "l"(p), "l"(pol));
    return v;
}

// 256-bit load: two adjacent float4 points in ONE instruction (32B aligned).
__device__ __forceinline__ void ldg256(const float4* p, float4& a, float4& b) {
    asm volatile("ld.global.nc.v8.b32 {%0,%1,%2,%3,%4,%5,%6,%7}, [%8];"
                 : "=f"(a.x), "=f"(a.y), "=f"(a.z), "=f"(a.w),
                   "=f"(b.x), "=f"(b.y), "=f"(b.z), "=f"(b.w)
                 : "l"(p));
}

// 256-bit evict_last store (sm_103a .v8.b32): 32B per instruction.
__device__ __forceinline__ void stg256_evict_last(uint4* p, uint4 a, uint4 b) {
    asm volatile("st.global.L2::evict_last.v8.b32 [%0], {%1,%2,%3,%4,%5,%6,%7,%8};"
                 :: "l"(p),
                    "r"(a.x), "r"(a.y), "r"(a.z), "r"(a.w),
                    "r"(b.x), "r"(b.y), "r"(b.z), "r"(b.w)
                 : "memory");
}

// Convert: thread = (x-group of 4, y, z-block of 4) with rolling z rows.
#define ZCH 4
#define CONV_XG (WS / 4)                        // 41
#define CONV_ZB (WS / ZCH)                      // 41
#define CONV_TOTAL (CONV_XG * WS * CONV_ZB)

__global__ void __launch_bounds__(256)
convert_kernel(const float* __restrict__ vol) {
    int t = blockIdx.x * blockDim.x + threadIdx.x;
    if (t >= CONV_TOTAL) return;
    int xg = t % CONV_XG;
    int yi = (t / CONV_XG) % WS;
    int zb = t / (CONV_XG * WS);

    int x  = WLO + (xg << 2);    // 16B-aligned
    int y  = WLO + yi;
    int z0 = WLO + zb * ZCH;

    const float* base0 = vol + ((z0 << 16) | (y << 8) | x);

    float4 a0 = __ldg((const float4*)base0);          float a0e = __ldg(base0 + 4);
    float4 a1 = __ldg((const float4*)(base0 + 256));  float a1e = __ldg(base0 + 256 + 4);
    float A0[5] = {a0.x, a0.y, a0.z, a0.w, a0e};
    float A1[5] = {a1.x, a1.y, a1.z, a1.w, a1e};

    uint4* dst = g_quad + (((zb * ZCH) * WS + yi) * WS + (xg << 2));

    #pragma unroll
    for (int dz = 0; dz < ZCH; dz++) {
        const float* basen = base0 + ((dz + 1) << 16);
        float4 b0 = __ldg((const float4*)basen);          float b0e = __ldg(basen + 4);
        float4 b1 = __ldg((const float4*)(basen + 256));  float b1e = __ldg(basen + 256 + 4);
        float B0[5] = {b0.x, b0.y, b0.z, b0.w, b0e};
        float B1[5] = {b1.x, b1.y, b1.z, b1.w, b1e};

        uint4 w[4];
        #pragma unroll
        for (int j = 0; j < 4; j++) {
            __half2 e0 = __floats2half2_rn(A0[j], A0[j + 1]);   // z,   y
            __half2 e1 = __floats2half2_rn(A1[j], A1[j + 1]);   // z,   y+1
            __half2 f0 = __floats2half2_rn(B0[j], B0[j + 1]);   // z+1, y
            __half2 f1 = __floats2half2_rn(B1[j], B1[j + 1]);   // z+1, y+1
            w[j].x = *(unsigned*)&e0; w[j].y = *(unsigned*)&e1;
            w[j].z = *(unsigned*)&f0; w[j].w = *(unsigned*)&f1;
        }
        stg256_evict_last(dst,     w[0], w[1]);
        stg256_evict_last(dst + 2, w[2], w[3]);

        dst += WS * WS;
        #pragma unroll
        for (int j = 0; j < 5; j++) { A0[j] = B0[j]; A1[j] = B1[j]; }
    }
}

// Exact fp32 path (out-of-window fallback and cs == 0).
__device__ __forceinline__ float gather(const float* __restrict__ vol,
                                        int z, int y, int x) {
    if ((unsigned)z < (unsigned)DHW &&
        (unsigned)y < (unsigned)DHW &&
        (unsigned)x < (unsigned)DHW) {
        return __ldg(vol + ((z << 16) | (y << 8) | x));
    }
    return 0.0f;
}

__device__ __noinline__ float sample_fp32(const float* __restrict__ vol,
                                          float ix, float iy, float iz) {
    float x0f = floorf(ix), y0f = floorf(iy), z0f = floorf(iz);
    float tx = ix - x0f, ty = iy - y0f, tz = iz - z0f;
    int x0 = (int)x0f, y0 = (int)y0f, z0 = (int)z0f;
    float v000 = gather(vol, z0, y0, x0);
    float v001 = gather(vol, z0, y0, x0 + 1);
    float v010 = gather(vol, z0, y0 + 1, x0);
    float v011 = gather(vol, z0, y0 + 1, x0 + 1);
    float v100 = gather(vol, z0 + 1, y0, x0);
    float v101 = gather(vol, z0 + 1, y0, x0 + 1);
    float v110 = gather(vol, z0 + 1, y0 + 1, x0);
    float v111 = gather(vol, z0 + 1, y0 + 1, x0 + 1);
    float c00 = v000 + tx * (v001 - v000);
    float c01 = v010 + tx * (v011 - v010);
    float c10 = v100 + tx * (v101 - v100);
    float c11 = v110 + tx * (v111 - v110);
    float c0  = c00 + ty * (c01 - c00);
    float c1  = c10 + ty * (c11 - c10);
    return c0 + tz * (c1 - c0);
}

// R14 sample kernel; only delta: one 256-bit load for the xyz pair.
__global__ void __launch_bounds__(256)
sample_kernel(const float4* __restrict__ xyz,
              const float* __restrict__ vol,
              const float* __restrict__ aabb,
              const int*   __restrict__ cspace,
              float* __restrict__ out,
              int n) {
    int base = (blockIdx.x * blockDim.x + threadIdx.x) * 2;
    if (base >= n) return;
    bool has1 = (base + 1) < n;

    float a0x = __ldg(aabb + 0), a0y = __ldg(aabb + 1), a0z = __ldg(aabb + 2);
    float a1x = __ldg(aabb + 3), a1y = __ldg(aabb + 4), a1z = __ldg(aabb + 5);
    float igx = 2.0f / (a1x - a0x);
    float igy = 2.0f / (a1y - a0y);
    float igz = 2.0f / (a1z - a0z);
    int cs = __ldg(cspace);
    const float half_span = 0.5f * (DHW - 1);
    uint64_t pol = make_policy_evict_last();

    float4 p[2];
    if (has1) {
        ldg256(xyz + base, p[0], p[1]);   // 32B contiguous, 32B aligned
    } else {
        p[0] = __ldcs(xyz + base);
        p[1] = p[0];
    }

    float tx[2], ty[2], tz[2];
    float fix[2], fiy[2], fiz[2];
    int   idx[2];

    #pragma unroll
    for (int j = 0; j < 2; j++) {
        float cx = (p[j].x - a0x) * igx - 1.0f;
        float cy = (p[j].y - a0y) * igy - 1.0f;
        float cz = (p[j].z - a0z) * igz - 1.0f;
        if (cs != 0) {
            float dist = fmaxf(fabsf(cx), fmaxf(fabsf(cy), fabsf(cz))) + 1e-8f;
            float scale = (dist > 1.0f) ? (2.0f - 1.0f / dist) : dist;
            float m = scale * 0.5f / dist;
            cx *= m; cy *= m; cz *= m;
        }
        float ix = (cx + 1.0f) * half_span;
        float iy = (cy + 1.0f) * half_span;
        float iz = (cz + 1.0f) * half_span;
        float x0f = floorf(ix), y0f = floorf(iy), z0f = floorf(iz);
        tx[j] = ix - x0f; ty[j] = iy - y0f; tz[j] = iz - z0f;
        fix[j] = ix; fiy[j] = iy; fiz[j] = iz;
        int xi = (int)x0f - WLO;
        int yi = (int)y0f - WLO;
        int zi = (int)z0f - WLO;
        idx[j] = (cs != 0 &&
                  (unsigned)xi < WS && (unsigned)yi < WS && (unsigned)zi < WS)
               ? ((zi * WS + yi) * WS + xi) : -1;
    }

    // One 16B evict_last gather per point, issued back-to-back.
    uint4 Q[2];
    Q[0] = (idx[0] >= 0) ? ldg_evict_last(g_quad + idx[0], pol)
                         : make_uint4(0u, 0u, 0u, 0u);
    Q[1] = (idx[1] >= 0) ? ldg_evict_last(g_quad + idx[1], pol)
                         : make_uint4(0u, 0u, 0u, 0u);

    float r[2];
    #pragma unroll
    for (int j = 0; j < 2; j++) {
        if (idx[j] >= 0) {
            float2 l0 = __half22float2(*(__half2*)&Q[j].x);
            float2 l1 = __half22float2(*(__half2*)&Q[j].y);
            float2 h0 = __half22float2(*(__half2*)&Q[j].z);
            float2 h1 = __half22float2(*(__half2*)&Q[j].w);
            float c00 = l0.x + tx[j] * (l0.y - l0.x);
            float c01 = l1.x + tx[j] * (l1.y - l1.x);
            float c10 = h0.x + tx[j] * (h0.y - h0.x);
            float c11 = h1.x + tx[j] * (h1.y - h1.x);
            float c0  = c00 + ty[j] * (c01 - c00);
            float c1  = c10 + ty[j] * (c11 - c10);
            r[j] = c0 + tz[j] * (c1 - c0);
        } else {
            r[j] = sample_fp32(vol, fix[j], fiy[j], fiz[j]);
        }
    }

    if (has1) {
        __stcs((float2*)(out + base), make_float2(r[0], r[1]));
    } else {
        out[base] = r[0];
    }
}

extern "C" void kernel_launch(void* const* d_in, const int* in_sizes, int n_in,
                              void* d_out, int out_size) {
    const float4* xyz  = (const float4*)d_in[0];
    const float*  vol  = (const float*)d_in[1];
    const float*  aabb = (const float*)d_in[2];
    const int*    cs   = (const int*)d_in[3];
    float* out = (float*)d_out;
    int n = out_size;

    convert_kernel<<<(CONV_TOTAL + 255) / 256, 256>>>(vol);

    int threads = 256;
    int pts_per_blk = threads * 2;
    int blocks = (n + pts_per_blk - 1) / pts_per_blk;
    sample_kernel<<<blocks, threads>>>(xyz, vol, aabb, cs, out, n);
}

// round 17
// speedup vs baseline: 1.3300x; 1.0877x over previous
#include <cuda_runtime.h>
#include <cuda_fp16.h>
#include <cstdint>

#define DHW 256

// Every-z 8-corner table over the contracted window (R14 design, measured
// sample 63.4us / convert 14.5us; only delta vs R14: xyz pair loaded with a
// single 256-bit EVICT_FIRST load — policy preserved, wavefronts halved).
// Exact bound: |coord| <= 0.625 -> ix in [47.8, 207.2] -> x0 in [47, 207].
// WLO=44 (multiple of 4 for aligned convert reads), WS=164 covers [44, 207].
// Entry (zi, yi, xi), fp16 pairs:
//  .x=(v[z][y][x],   v[z][y][x+1])    .y=(v[z][y+1][x],   v[z][y+1][x+1])
//  .z=(v[z+1][y][x], v[z+1][y][x+1])  .w=(v[z+1][y+1][x], v[z+1][y+1][x+1])
// One aligned 16B load = all 8 corners. 164^3*16B = 70.6 MB.
#define WLO 44
#define WS  164
__device__ __align__(32) uint4 g_quad[WS * WS * WS];

__device__ __forceinline__ uint64_t make_policy_evict_last() {
    uint64_t pol;
    asm("createpolicy.fractional.L2::evict_last.b64 %0, 1.0;" : "=l"(pol));
    return pol;
}

__device__ __forceinline__ uint4 ldg_evict_last(const uint4* p, uint64_t pol) {
    uint4 v;
    asm volatile("ld.global.nc.L2::cache_hint.v4.u32 {%0,%1,%2,%3}, [%4], %5;"
                 : "=r"(v.x), "=r"(v.y), "=r"(v.z), "=r"(v.w)
                 : "l"(p), "l"(pol));
    return v;
}

// 256-bit EVICT_FIRST load: two adjacent float4 points, one instruction,
// streaming L2 policy (doesn't displace the resident table).
__device__ __forceinline__ void ldg256_evict_first(const float4* p,
                                                   float4& a, float4& b) {
    asm volatile("ld.global.nc.L2::evict_first.v8.b32 "
                 "{%0,%1,%2,%3,%4,%5,%6,%7}, [%8];"
                 : "=f"(a.x), "=f"(a.y), "=f"(a.z), "=f"(a.w),
                   "=f"(b.x), "=f"(b.y), "=f"(b.z), "=f"(b.w)
                 : "l"(p));
}

// 256-bit evict_last store (sm_103a .v8.b32): 32B per instruction.
__device__ __forceinline__ void stg256_evict_last(uint4* p, uint4 a, uint4 b) {
    asm volatile("st.global.L2::evict_last.v8.b32 [%0], {%1,%2,%3,%4,%5,%6,%7,%8};"
                 :: "l"(p),
                    "r"(a.x), "r"(a.y), "r"(a.z), "r"(a.w),
                    "r"(b.x), "r"(b.y), "r"(b.z), "r"(b.w)
                 : "memory");
}

// Convert: thread = (x-group of 4, y, z-block of 4) with rolling z rows.
#define ZCH 4
#define CONV_XG (WS / 4)                        // 41
#define CONV_ZB (WS / ZCH)                      // 41
#define CONV_TOTAL (CONV_XG * WS * CONV_ZB)

__global__ void __launch_bounds__(256)
convert_kernel(const float* __restrict__ vol) {
    int t = blockIdx.x * blockDim.x + threadIdx.x;
    if (t >= CONV_TOTAL) return;
    int xg = t % CONV_XG;
    int yi = (t / CONV_XG) % WS;
    int zb = t / (CONV_XG * WS);

    int x  = WLO + (xg << 2);    // 16B-aligned
    int y  = WLO + yi;
    int z0 = WLO + zb * ZCH;

    const float* base0 = vol + ((z0 << 16) | (y << 8) | x);

    float4 a0 = __ldg((const float4*)base0);          float a0e = __ldg(base0 + 4);
    float4 a1 = __ldg((const float4*)(base0 + 256));  float a1e = __ldg(base0 + 256 + 4);
    float A0[5] = {a0.x, a0.y, a0.z, a0.w, a0e};
    float A1[5] = {a1.x, a1.y, a1.z, a1.w, a1e};

    uint4* dst = g_quad + (((zb * ZCH) * WS + yi) * WS + (xg << 2));

    #pragma unroll
    for (int dz = 0; dz < ZCH; dz++) {
        const float* basen = base0 + ((dz + 1) << 16);
        float4 b0 = __ldg((const float4*)basen);          float b0e = __ldg(basen + 4);
        float4 b1 = __ldg((const float4*)(basen + 256));  float b1e = __ldg(basen + 256 + 4);
        float B0[5] = {b0.x, b0.y, b0.z, b0.w, b0e};
        float B1[5] = {b1.x, b1.y, b1.z, b1.w, b1e};

        uint4 w[4];
        #pragma unroll
        for (int j = 0; j < 4; j++) {
            __half2 e0 = __floats2half2_rn(A0[j], A0[j + 1]);   // z,   y
            __half2 e1 = __floats2half2_rn(A1[j], A1[j + 1]);   // z,   y+1
            __half2 f0 = __floats2half2_rn(B0[j], B0[j + 1]);   // z+1, y
            __half2 f1 = __floats2half2_rn(B1[j], B1[j + 1]);   // z+1, y+1
            w[j].x = *(unsigned*)&e0; w[j].y = *(unsigned*)&e1;
            w[j].z = *(unsigned*)&f0; w[j].w = *(unsigned*)&f1;
        }
        stg256_evict_last(dst,     w[0], w[1]);
        stg256_evict_last(dst + 2, w[2], w[3]);

        dst += WS * WS;
        #pragma unroll
        for (int j = 0; j < 5; j++) { A0[j] = B0[j]; A1[j] = B1[j]; }
    }
}

// Exact fp32 path (out-of-window fallback and cs == 0).
__device__ __forceinline__ float gather(const float* __restrict__ vol,
                                        int z, int y, int x) {
    if ((unsigned)z < (unsigned)DHW &&
        (unsigned)y < (unsigned)DHW &&
        (unsigned)x < (unsigned)DHW) {
        return __ldg(vol + ((z << 16) | (y << 8) | x));
    }
    return 0.0f;
}

__device__ __noinline__ float sample_fp32(const float* __restrict__ vol,
                                          float ix, float iy, float iz) {
    float x0f = floorf(ix), y0f = floorf(iy), z0f = floorf(iz);
    float tx = ix - x0f, ty = iy - y0f, tz = iz - z0f;
    int x0 = (int)x0f, y0 = (int)y0f, z0 = (int)z0f;
    float v000 = gather(vol, z0, y0, x0);
    float v001 = gather(vol, z0, y0, x0 + 1);
    float v010 = gather(vol, z0, y0 + 1, x0);
    float v011 = gather(vol, z0, y0 + 1, x0 + 1);
    float v100 = gather(vol, z0 + 1, y0, x0);
    float v101 = gather(vol, z0 + 1, y0, x0 + 1);
    float v110 = gather(vol, z0 + 1, y0 + 1, x0);
    float v111 = gather(vol, z0 + 1, y0 + 1, x0 + 1);
    float c00 = v000 + tx * (v001 - v000);
    float c01 = v010 + tx * (v011 - v010);
    float c10 = v100 + tx * (v101 - v100);
    float c11 = v110 + tx * (v111 - v110);
    float c0  = c00 + ty * (c01 - c00);
    float c1  = c10 + ty * (c11 - c10);
    return c0 + tz * (c1 - c0);
}

// R14 sample kernel; only delta: evict_first 256-bit load for the xyz pair.
__global__ void __launch_bounds__(256)
sample_kernel(const float4* __restrict__ xyz,
              const float* __restrict__ vol,
              const float* __restrict__ aabb,
              const int*   __restrict__ cspace,
              float* __restrict__ out,
              int n) {
    int base = (blockIdx.x * blockDim.x + threadIdx.x) * 2;
    if (base >= n) return;
    bool has1 = (base + 1) < n;

    float a0x = __ldg(aabb + 0), a0y = __ldg(aabb + 1), a0z = __ldg(aabb + 2);
    float a1x = __ldg(aabb + 3), a1y = __ldg(aabb + 4), a1z = __ldg(aabb + 5);
    float igx = 2.0f / (a1x - a0x);
    float igy = 2.0f / (a1y - a0y);
    float igz = 2.0f / (a1z - a0z);
    int cs = __ldg(cspace);
    const float half_span = 0.5f * (DHW - 1);
    uint64_t pol = make_policy_evict_last();

    float4 p[2];
    if (has1) {
        ldg256_evict_first(xyz + base, p[0], p[1]);  // 32B aligned pair
    } else {
        p[0] = __ldcs(xyz + base);
        p[1] = p[0];
    }

    float tx[2], ty[2], tz[2];
    float fix[2], fiy[2], fiz[2];
    int   idx[2];

    #pragma unroll
    for (int j = 0; j < 2; j++) {
        float cx = (p[j].x - a0x) * igx - 1.0f;
        float cy = (p[j].y - a0y) * igy - 1.0f;
        float cz = (p[j].z - a0z) * igz - 1.0f;
        if (cs != 0) {
            float dist = fmaxf(fabsf(cx), fmaxf(fabsf(cy), fabsf(cz))) + 1e-8f;
            float scale = (dist > 1.0f) ? (2.0f - 1.0f / dist) : dist;
            float m = scale * 0.5f / dist;
            cx *= m; cy *= m; cz *= m;
        }
        float ix = (cx + 1.0f) * half_span;
        float iy = (cy + 1.0f) * half_span;
        float iz = (cz + 1.0f) * half_span;
        float x0f = floorf(ix), y0f = floorf(iy), z0f = floorf(iz);
        tx[j] = ix - x0f; ty[j] = iy - y0f; tz[j] = iz - z0f;
        fix[j] = ix; fiy[j] = iy; fiz[j] = iz;
        int xi = (int)x0f - WLO;
        int yi = (int)y0f - WLO;
        int zi = (int)z0f - WLO;
        idx[j] = (cs != 0 &&
                  (unsigned)xi < WS && (unsigned)yi < WS && (unsigned)zi < WS)
               ? ((zi * WS + yi) * WS + xi) : -1;
    }

    // One 16B evict_last gather per point, issued back-to-back.
    uint4 Q[2];
    Q[0] = (idx[0] >= 0) ? ldg_evict_last(g_quad + idx[0], pol)
                         : make_uint4(0u, 0u, 0u, 0u);
    Q[1] = (idx[1] >= 0) ? ldg_evict_last(g_quad + idx[1], pol)
                         : make_uint4(0u, 0u, 0u, 0u);

    float r[2];
    #pragma unroll
    for (int j = 0; j < 2; j++) {
        if (idx[j] >= 0) {
            float2 l0 = __half22float2(*(__half2*)&Q[j].x);
            float2 l1 = __half22float2(*(__half2*)&Q[j].y);
            float2 h0 = __half22float2(*(__half2*)&Q[j].z);
            float2 h1 = __half22float2(*(__half2*)&Q[j].w);
            float c00 = l0.x + tx[j] * (l0.y - l0.x);
            float c01 = l1.x + tx[j] * (l1.y - l1.x);
            float c10 = h0.x + tx[j] * (h0.y - h0.x);
            float c11 = h1.x + tx[j] * (h1.y - h1.x);
            float c0  = c00 + ty[j] * (c01 - c00);
            float c1  = c10 + ty[j] * (c11 - c10);
            r[j] = c0 + tz[j] * (c1 - c0);
        } else {
            r[j] = sample_fp32(vol, fix[j], fiy[j], fiz[j]);
        }
    }

    if (has1) {
        __stcs((float2*)(out + base), make_float2(r[0], r[1]));
    } else {
        out[base] = r[0];
    }
}

extern "C" void kernel_launch(void* const* d_in, const int* in_sizes, int n_in,
                              void* d_out, int out_size) {
    const float4* xyz  = (const float4*)d_in[0];
    const float*  vol  = (const float*)d_in[1];
    const float*  aabb = (const float*)d_in[2];
    const int*    cs   = (const int*)d_in[3];
    float* out = (float*)d_out;
    int n = out_size;

    convert_kernel<<<(CONV_TOTAL + 255) / 256, 256>>>(vol);

    int threads = 256;
    int pts_per_blk = threads * 2;
    int blocks = (n + pts_per_blk - 1) / pts_per_blk;
    sample_kernel<<<blocks, threads>>>(xyz, vol, aabb, cs, out, n);
}